// round 14
// baseline (speedup 1.0000x reference)
#include <cuda_runtime.h>
#include <cuda_fp16.h>
#include <cstdint>

#define BATCH 2048
#define HID   1024
#define FFN   4096
#define NE    8

// ---- device scratch ----
__device__ int    g_cnt[NE];
__device__ int    g_tok[NE][BATCH];
__device__ float  g_wgt[NE][BATCH];
__device__ int    g_flags[4];
__device__ __half g_H[(size_t)NE * BATCH * FFN];    // 128 MiB fp16 intermediate
__device__ __half g_WA[(size_t)NE * HID * FFN];     // 64 MiB: fp16(bigA)
__device__ __half g_WB[(size_t)NE * HID * FFN];     // 64 MiB: fp16(bigB)
__device__ __half g_Xh[(size_t)BATCH * HID];        // 4 MiB: fp16(X)

// ---- helpers ----
static __device__ __forceinline__ uint32_t smem_u32(const void* p) {
    uint32_t a;
    asm("{ .reg .u64 t; cvta.to.shared.u64 t, %1; cvt.u32.u64 %0, t; }" : "=r"(a) : "l"(p));
    return a;
}
static __device__ __forceinline__ void cp16(uint32_t dst, const void* src) {
    asm volatile("cp.async.cg.shared.global [%0], [%1], 16;" :: "r"(dst), "l"(src));
}
static __device__ __forceinline__ void cp_commit() {
    asm volatile("cp.async.commit_group;" ::: "memory");
}
static __device__ __forceinline__ void cp_wait1() {
    asm volatile("cp.async.wait_group 1;" ::: "memory");
}
static __device__ __forceinline__ void ldsm_x4(unsigned* r, uint32_t addr) {
    asm volatile("ldmatrix.sync.aligned.m8n8.x4.shared.b16 {%0,%1,%2,%3}, [%4];"
                 : "=r"(r[0]), "=r"(r[1]), "=r"(r[2]), "=r"(r[3]) : "r"(addr));
}
static __device__ __forceinline__ void ldsm_x4_t(unsigned* r, uint32_t addr) {
    asm volatile("ldmatrix.sync.aligned.m8n8.x4.trans.shared.b16 {%0,%1,%2,%3}, [%4];"
                 : "=r"(r[0]), "=r"(r[1]), "=r"(r[2]), "=r"(r[3]) : "r"(addr));
}
static __device__ __forceinline__ void mma16816(float* c, const unsigned* a,
                                                const unsigned* b) {
    asm volatile(
        "mma.sync.aligned.m16n8k16.row.col.f32.f16.f16.f32 "
        "{%0,%1,%2,%3}, {%4,%5,%6,%7}, {%8,%9}, {%0,%1,%2,%3};"
        : "+f"(c[0]), "+f"(c[1]), "+f"(c[2]), "+f"(c[3])
        : "r"(a[0]), "r"(a[1]), "r"(a[2]), "r"(a[3]), "r"(b[0]), "r"(b[1]));
}
static __device__ __forceinline__ float silu(float v) {
    return v / (1.0f + __expf(-v));
}

// smem tile strides (halves) — padded, conflict-free for ldmatrix
#define ASTR 40     // 64 x 32 A tile
#define BSTR 136    // 32 x 128 B tile
#define ASZ  (64 * ASTR * 2)           // 5120 B
#define BSZ  (32 * BSTR * 2)           // 8704 B
#define STG  (ASZ + BSZ)               // 13824 B
#define NSTG 3
#define SMEM_BYTES (NSTG * STG)        // 41472 B (dynamic) -> 2 CTAs/SM

// ---------------------------------------------------------------------------
__device__ int classify_small(const unsigned* w) {
    bool i64 = true, i32 = true;
    for (int j = 0; j < 32; j++) {
        unsigned v = w[j];
        if (j & 1) { if (v != 0u) i64 = false; }
        else       { if (v >= 8u) i64 = false; }
        if (v >= 8u) i32 = false;
    }
    if (i64) return 1;
    if (i32) return 2;
    return 0;
}

__global__ void k_detect(const unsigned* smallA, const unsigned* smallB,
                         const float* bigA, const float* bigB) {
    __shared__ float sA[256], sB[256];
    int t = threadIdx.x;
    float a = 0.f, b = 0.f;
    for (int i = t; i < 4096; i += 256) { a += fabsf(bigA[i]); b += fabsf(bigB[i]); }
    sA[t] = a; sB[t] = b;
    __syncthreads();
    for (int s = 128; s > 0; s >>= 1) {
        if (t < s) { sA[t] += sA[t + s]; sB[t] += sB[t + s]; }
        __syncthreads();
    }
    if (t < NE) g_cnt[t] = 0;
    if (t == 0) {
        g_flags[2] = (sA[0] > sB[0]) ? 1 : 0;   // larger scale (H^-0.5) => w1
        int tA = classify_small(smallA);
        if (tA != 0) { g_flags[0] = 1; g_flags[1] = (tA == 1); }
        else {
            int tB = classify_small(smallB);
            g_flags[0] = 0; g_flags[1] = (tB == 1);
        }
    }
}

__global__ void k_route(const void* smallA, const void* smallB) {
    int b = blockIdx.x * blockDim.x + threadIdx.x;
    if (b >= BATCH) return;
    const void*  idxp = g_flags[0] ? smallA : smallB;
    const float* rw   = (const float*)(g_flags[0] ? smallB : smallA);
    int e0, e1;
    if (g_flags[1]) {
        e0 = (int)((const long long*)idxp)[b * 2 + 0];
        e1 = (int)((const long long*)idxp)[b * 2 + 1];
    } else {
        e0 = ((const int*)idxp)[b * 2 + 0];
        e1 = ((const int*)idxp)[b * 2 + 1];
    }
    float w0 = rw[b * 2 + 0];
    float w1 = rw[b * 2 + 1];
    if (e0 == e1) {
        int p = atomicAdd(&g_cnt[e0], 1);
        g_tok[e0][p] = b; g_wgt[e0][p] = w0 + w1;
    } else {
        int p = atomicAdd(&g_cnt[e0], 1);
        g_tok[e0][p] = b; g_wgt[e0][p] = w0;
        p = atomicAdd(&g_cnt[e1], 1);
        g_tok[e1][p] = b; g_wgt[e1][p] = w1;
    }
}

// fp32 -> fp16 grid-stride converter (8 elems / thread / iter)
__global__ void k_cvt(const float4* __restrict__ src, uint4* __restrict__ dst,
                      int n8) {
    int i = blockIdx.x * blockDim.x + threadIdx.x;
    int stride = gridDim.x * blockDim.x;
    for (; i < n8; i += stride) {
        float4 v0 = src[i * 2], v1 = src[i * 2 + 1];
        __half2 h0 = __floats2half2_rn(v0.x, v0.y);
        __half2 h1 = __floats2half2_rn(v0.z, v0.w);
        __half2 h2 = __floats2half2_rn(v1.x, v1.y);
        __half2 h3 = __floats2half2_rn(v1.z, v1.w);
        uint4 o;
        o.x = *(uint32_t*)&h0; o.y = *(uint32_t*)&h1;
        o.z = *(uint32_t*)&h2; o.w = *(uint32_t*)&h3;
        dst[i] = o;
    }
}

// ---------------------------------------------------------------------------
// GEMM1: H[e,pos,f] = silu(X[tok] . W1[e][:,f]); 256 thr, CTA 64x128, 2 CTA/SM
__global__ __launch_bounds__(256, 2)
void k_gemm1() {
    const __half* W1 = g_flags[2] ? g_WA : g_WB;
    int e    = blockIdx.z;
    int cnt  = g_cnt[e];
    int row0 = blockIdx.y * 64;
    if (row0 >= cnt) return;
    int col0 = blockIdx.x * 128;

    extern __shared__ char dyn[];
    __shared__ int stok[64];

    int tid = threadIdx.x, lane = tid & 31, wid = tid >> 5;
    if (tid < 64) {
        int r = row0 + tid;
        stok[tid] = (r < cnt) ? g_tok[e][r] : 0;
    }
    __syncthreads();

    const __half* W = W1 + (size_t)e * HID * FFN + col0;
    uint32_t sb = smem_u32(dyn);

    // copy mapping: A 64x32 (1 cp16/thread), B 32x128 (2 cp16/thread)
    int arow = tid >> 2, aoff = (tid & 3) * 8;
    const __half* Asrc = g_Xh + (size_t)stok[arow] * HID + aoff;
    int brow = tid >> 4, bch = (tid & 15) * 8;
    const __half* Bsrc = W + (size_t)brow * FFN + bch;

    uint32_t adst  = (uint32_t)(arow * ASTR + aoff) * 2;
    uint32_t bdst0 = (uint32_t)(ASZ) + (uint32_t)(brow * BSTR + bch) * 2;
    uint32_t bdst1 = (uint32_t)(ASZ) + (uint32_t)((brow + 16) * BSTR + bch) * 2;

    // fragment addressing: warp grid 2m x 4n, warp tile 32x32
    int wm = wid & 1, wn = wid >> 1;
    int grp = lane >> 2, tid4 = lane & 3;
    uint32_t aoffB = (uint32_t)(((wm * 32 + (lane & 15)) * ASTR) + ((lane >> 4) * 8)) * 2;
    uint32_t boffB = (uint32_t)(ASZ) +
                     (uint32_t)((((lane & 7) + ((lane >> 3) & 1) * 8) * BSTR) +
                                wn * 32 + (lane >> 4) * 8) * 2;

    const int NIT = HID / 32;

    // prologue: stages 0,1
#pragma unroll
    for (int s = 0; s < 2; s++) {
        uint32_t st = sb + s * STG;
        int k0 = s * 32;
        cp16(st + adst, Asrc + k0);
        cp16(st + bdst0, Bsrc + (size_t)k0 * FFN);
        cp16(st + bdst1, Bsrc + (size_t)(k0 + 16) * FFN);
        cp_commit();
    }

    float acc[2][4][4] = {};
    int stg = 0;
    for (int it = 0; it < NIT; it++) {
        cp_wait1();
        __syncthreads();
        if (it + 2 < NIT) {
            uint32_t st = sb + ((stg + 2) % NSTG) * STG;
            int k0 = (it + 2) * 32;
            cp16(st + adst, Asrc + k0);
            cp16(st + bdst0, Bsrc + (size_t)k0 * FFN);
            cp16(st + bdst1, Bsrc + (size_t)(k0 + 16) * FFN);
        }
        cp_commit();

        uint32_t aB = sb + stg * STG + aoffB;
        uint32_t bB = sb + stg * STG + boffB;
#pragma unroll
        for (int kk = 0; kk < 2; kk++) {
            unsigned afr[2][4];
            ldsm_x4(afr[0], aB + kk * 32);
            ldsm_x4(afr[1], aB + 16 * ASTR * 2 + kk * 32);
            unsigned bfr[4][2];
#pragma unroll
            for (int j2 = 0; j2 < 2; j2++) {
                unsigned t[4];
                ldsm_x4_t(t, bB + kk * 16 * BSTR * 2 + j2 * 32);
                bfr[j2 * 2][0] = t[0]; bfr[j2 * 2][1] = t[1];
                bfr[j2 * 2 + 1][0] = t[2]; bfr[j2 * 2 + 1][1] = t[3];
            }
#pragma unroll
            for (int mt = 0; mt < 2; mt++)
#pragma unroll
                for (int j = 0; j < 4; j++)
                    mma16816(acc[mt][j], afr[mt], bfr[j]);
        }
        stg = (stg + 1) % NSTG;
    }

    // epilogue: silu -> fp16 g_H
#pragma unroll
    for (int mt = 0; mt < 2; mt++) {
        int rb = row0 + wm * 32 + mt * 16 + grp;
#pragma unroll
        for (int j = 0; j < 4; j++) {
            int cg = col0 + wn * 32 + j * 8 + tid4 * 2;
            float* c = acc[mt][j];
            if (rb < cnt) {
                __half2* Hr = (__half2*)(g_H + ((size_t)e * BATCH + rb) * FFN + cg);
                *Hr = __floats2half2_rn(silu(c[0]), silu(c[1]));
            }
            if (rb + 8 < cnt) {
                __half2* Hr = (__half2*)(g_H + ((size_t)e * BATCH + rb + 8) * FFN + cg);
                *Hr = __floats2half2_rn(silu(c[2]), silu(c[3]));
            }
        }
    }
}

// ---------------------------------------------------------------------------
// GEMM2: out[tok] += wgt * (H[e,pos,:] . W2[e][:,h]); 256 thr, 64x128, 2 CTA/SM
__global__ __launch_bounds__(256, 2)
void k_gemm2(float* __restrict__ out) {
    const __half* W2 = g_flags[2] ? g_WB : g_WA;
    int e    = blockIdx.z;
    int cnt  = g_cnt[e];
    int row0 = blockIdx.y * 64;
    if (row0 >= cnt) return;
    int col0 = blockIdx.x * 128;

    extern __shared__ char dyn[];
    __shared__ int   stok[64];
    __shared__ float swt[64];

    int tid = threadIdx.x, lane = tid & 31, wid = tid >> 5;
    if (tid < 64) {
        int r = row0 + tid;
        stok[tid] = (r < cnt) ? g_tok[e][r] : 0;
        swt[tid]  = (r < cnt) ? g_wgt[e][r] : 0.0f;
    }
    __syncthreads();

    const __half* W = W2 + (size_t)e * HID * FFN + col0;
    uint32_t sb = smem_u32(dyn);

    int arow = tid >> 2, aoff = (tid & 3) * 8;
    const __half* Asrc = g_H + ((size_t)e * BATCH + row0 + arow) * FFN + aoff;
    int brow = tid >> 4, bch = (tid & 15) * 8;
    const __half* Bsrc = W + (size_t)brow * HID + bch;

    uint32_t adst  = (uint32_t)(arow * ASTR + aoff) * 2;
    uint32_t bdst0 = (uint32_t)(ASZ) + (uint32_t)(brow * BSTR + bch) * 2;
    uint32_t bdst1 = (uint32_t)(ASZ) + (uint32_t)((brow + 16) * BSTR + bch) * 2;

    int wm = wid & 1, wn = wid >> 1;
    int grp = lane >> 2, tid4 = lane & 3;
    uint32_t aoffB = (uint32_t)(((wm * 32 + (lane & 15)) * ASTR) + ((lane >> 4) * 8)) * 2;
    uint32_t boffB = (uint32_t)(ASZ) +
                     (uint32_t)((((lane & 7) + ((lane >> 3) & 1) * 8) * BSTR) +
                                wn * 32 + (lane >> 4) * 8) * 2;

    const int NIT = FFN / 32;

#pragma unroll
    for (int s = 0; s < 2; s++) {
        uint32_t st = sb + s * STG;
        int k0 = s * 32;
        cp16(st + adst, Asrc + k0);
        cp16(st + bdst0, Bsrc + (size_t)k0 * HID);
        cp16(st + bdst1, Bsrc + (size_t)(k0 + 16) * HID);
        cp_commit();
    }

    float acc[2][4][4] = {};
    int stg = 0;
    for (int it = 0; it < NIT; it++) {
        cp_wait1();
        __syncthreads();
        if (it + 2 < NIT) {
            uint32_t st = sb + ((stg + 2) % NSTG) * STG;
            int k0 = (it + 2) * 32;
            cp16(st + adst, Asrc + k0);
            cp16(st + bdst0, Bsrc + (size_t)k0 * HID);
            cp16(st + bdst1, Bsrc + (size_t)(k0 + 16) * HID);
        }
        cp_commit();

        uint32_t aB = sb + stg * STG + aoffB;
        uint32_t bB = sb + stg * STG + boffB;
#pragma unroll
        for (int kk = 0; kk < 2; kk++) {
            unsigned afr[2][4];
            ldsm_x4(afr[0], aB + kk * 32);
            ldsm_x4(afr[1], aB + 16 * ASTR * 2 + kk * 32);
            unsigned bfr[4][2];
#pragma unroll
            for (int j2 = 0; j2 < 2; j2++) {
                unsigned t[4];
                ldsm_x4_t(t, bB + kk * 16 * BSTR * 2 + j2 * 32);
                bfr[j2 * 2][0] = t[0]; bfr[j2 * 2][1] = t[1];
                bfr[j2 * 2 + 1][0] = t[2]; bfr[j2 * 2 + 1][1] = t[3];
            }
#pragma unroll
            for (int mt = 0; mt < 2; mt++)
#pragma unroll
                for (int j = 0; j < 4; j++)
                    mma16816(acc[mt][j], afr[mt], bfr[j]);
        }
        stg = (stg + 1) % NSTG;
    }

    // epilogue: weighted atomic scatter
#pragma unroll
    for (int mt = 0; mt < 2; mt++) {
        int lr = wm * 32 + mt * 16 + grp;
#pragma unroll
        for (int j = 0; j < 4; j++) {
            int cg = col0 + wn * 32 + j * 8 + tid4 * 2;
            float* c = acc[mt][j];
            if (row0 + lr < cnt) {
                int   t = stok[lr];
                float w = swt[lr];
                atomicAdd(&out[(size_t)t * HID + cg],     w * c[0]);
                atomicAdd(&out[(size_t)t * HID + cg + 1], w * c[1]);
            }
            if (row0 + lr + 8 < cnt) {
                int   t = stok[lr + 8];
                float w = swt[lr + 8];
                atomicAdd(&out[(size_t)t * HID + cg],     w * c[2]);
                atomicAdd(&out[(size_t)t * HID + cg + 1], w * c[3]);
            }
        }
    }
}

// ---------------------------------------------------------------------------
extern "C" void kernel_launch(void* const* d_in, const int* in_sizes, int n_in,
                              void* d_out, int out_size) {
    const float* X = nullptr;
    const void*  smallbuf[2] = {nullptr, nullptr};
    const float* bigbuf[2]   = {nullptr, nullptr};
    int ns = 0, nb = 0;
    for (int i = 0; i < n_in; i++) {
        long long s = in_sizes[i];
        if (s == (long long)BATCH * HID)            X = (const float*)d_in[i];
        else if (s == (long long)BATCH * 2)         { if (ns < 2) smallbuf[ns++] = d_in[i]; }
        else if (s == (long long)NE * HID * FFN)    { if (nb < 2) bigbuf[nb++] = (const float*)d_in[i]; }
    }
    float* out = (float*)d_out;

    cudaFuncSetAttribute(k_gemm1, cudaFuncAttributeMaxDynamicSharedMemorySize, SMEM_BYTES);
    cudaFuncSetAttribute(k_gemm2, cudaFuncAttributeMaxDynamicSharedMemorySize, SMEM_BYTES);

    __half *dWA, *dWB, *dXh;
    cudaGetSymbolAddress((void**)&dWA, g_WA);
    cudaGetSymbolAddress((void**)&dWB, g_WB);
    cudaGetSymbolAddress((void**)&dXh, g_Xh);

    cudaMemsetAsync(out, 0, (size_t)out_size * sizeof(float));
    k_detect<<<1, 256>>>((const unsigned*)smallbuf[0], (const unsigned*)smallbuf[1],
                         bigbuf[0], bigbuf[1]);
    k_route<<<(BATCH + 255) / 256, 256>>>(smallbuf[0], smallbuf[1]);

    int n8w = NE * HID * FFN / 8;
    k_cvt<<<1184, 256>>>((const float4*)bigbuf[0], (uint4*)dWA, n8w);
    k_cvt<<<1184, 256>>>((const float4*)bigbuf[1], (uint4*)dWB, n8w);
    k_cvt<<<256, 256>>>((const float4*)X, (uint4*)dXh, BATCH * HID / 8);

    k_gemm1<<<dim3(FFN / 128, BATCH / 64, NE), 256, SMEM_BYTES>>>();
    k_gemm2<<<dim3(HID / 128, BATCH / 64, NE), 256, SMEM_BYTES>>>(out);
}

// round 15
// speedup vs baseline: 1.0052x; 1.0052x over previous
#include <cuda_runtime.h>
#include <cuda_fp16.h>
#include <cstdint>

#define BATCH 2048
#define HID   1024
#define FFN   4096
#define NE    8

// ---- device scratch ----
__device__ int    g_cnt[NE];
__device__ int    g_tok[NE][BATCH];
__device__ float  g_wgt[NE][BATCH];
__device__ int    g_flags[4];
__device__ __half g_H[(size_t)NE * BATCH * FFN];    // 128 MiB fp16 intermediate
__device__ __half g_W1h[(size_t)NE * HID * FFN];    // 64 MiB: fp16(W1)
__device__ __half g_W2h[(size_t)NE * HID * FFN];    // 64 MiB: fp16(W2)
__device__ __half g_Xh[(size_t)BATCH * HID];        // 4 MiB: fp16(X)

// ---- helpers ----
static __device__ __forceinline__ uint32_t smem_u32(const void* p) {
    uint32_t a;
    asm("{ .reg .u64 t; cvta.to.shared.u64 t, %1; cvt.u32.u64 %0, t; }" : "=r"(a) : "l"(p));
    return a;
}
static __device__ __forceinline__ void cp16(uint32_t dst, const void* src) {
    asm volatile("cp.async.cg.shared.global [%0], [%1], 16;" :: "r"(dst), "l"(src));
}
static __device__ __forceinline__ void cp_commit() {
    asm volatile("cp.async.commit_group;" ::: "memory");
}
static __device__ __forceinline__ void cp_wait1() {
    asm volatile("cp.async.wait_group 1;" ::: "memory");
}
static __device__ __forceinline__ void ldsm_x4(unsigned* r, uint32_t addr) {
    asm volatile("ldmatrix.sync.aligned.m8n8.x4.shared.b16 {%0,%1,%2,%3}, [%4];"
                 : "=r"(r[0]), "=r"(r[1]), "=r"(r[2]), "=r"(r[3]) : "r"(addr));
}
static __device__ __forceinline__ void ldsm_x4_t(unsigned* r, uint32_t addr) {
    asm volatile("ldmatrix.sync.aligned.m8n8.x4.trans.shared.b16 {%0,%1,%2,%3}, [%4];"
                 : "=r"(r[0]), "=r"(r[1]), "=r"(r[2]), "=r"(r[3]) : "r"(addr));
}
static __device__ __forceinline__ void mma16816(float* c, const unsigned* a,
                                                const unsigned* b) {
    asm volatile(
        "mma.sync.aligned.m16n8k16.row.col.f32.f16.f16.f32 "
        "{%0,%1,%2,%3}, {%4,%5,%6,%7}, {%8,%9}, {%0,%1,%2,%3};"
        : "+f"(c[0]), "+f"(c[1]), "+f"(c[2]), "+f"(c[3])
        : "r"(a[0]), "r"(a[1]), "r"(a[2]), "r"(a[3]), "r"(b[0]), "r"(b[1]));
}
static __device__ __forceinline__ float silu(float v) {
    return v / (1.0f + __expf(-v));
}

// smem tile strides (halves) — padded, conflict-free for ldmatrix
#define ASTR 40     // 64 x 32 A tile
#define BSTR 136    // 32 x 128 B tile
#define ASZ  (64 * ASTR * 2)           // 5120 B
#define BSZ  (32 * BSTR * 2)           // 8704 B
#define STG  (ASZ + BSZ)               // 13824 B
#define NSTG 3
#define SMEM_BYTES (NSTG * STG)        // 41472 B (dynamic) -> 2 CTAs/SM

// ---------------------------------------------------------------------------
__device__ int classify_small(const unsigned* w) {
    bool i64 = true, i32 = true;
    for (int j = 0; j < 32; j++) {
        unsigned v = w[j];
        if (j & 1) { if (v != 0u) i64 = false; }
        else       { if (v >= 8u) i64 = false; }
        if (v >= 8u) i32 = false;
    }
    if (i64) return 1;
    if (i32) return 2;
    return 0;
}

__global__ void k_detect(const unsigned* smallA, const unsigned* smallB,
                         const float* bigA, const float* bigB) {
    __shared__ float sA[256], sB[256];
    int t = threadIdx.x;
    float a = 0.f, b = 0.f;
    for (int i = t; i < 4096; i += 256) { a += fabsf(bigA[i]); b += fabsf(bigB[i]); }
    sA[t] = a; sB[t] = b;
    __syncthreads();
    for (int s = 128; s > 0; s >>= 1) {
        if (t < s) { sA[t] += sA[t + s]; sB[t] += sB[t + s]; }
        __syncthreads();
    }
    if (t < NE) g_cnt[t] = 0;
    if (t == 0) {
        g_flags[2] = (sA[0] > sB[0]) ? 1 : 0;   // larger scale (H^-0.5) => w1
        int tA = classify_small(smallA);
        if (tA != 0) { g_flags[0] = 1; g_flags[1] = (tA == 1); }
        else {
            int tB = classify_small(smallB);
            g_flags[0] = 0; g_flags[1] = (tB == 1);
        }
    }
}

__global__ void k_route(const void* smallA, const void* smallB) {
    int b = blockIdx.x * blockDim.x + threadIdx.x;
    if (b >= BATCH) return;
    const void*  idxp = g_flags[0] ? smallA : smallB;
    const float* rw   = (const float*)(g_flags[0] ? smallB : smallA);
    int e0, e1;
    if (g_flags[1]) {
        e0 = (int)((const long long*)idxp)[b * 2 + 0];
        e1 = (int)((const long long*)idxp)[b * 2 + 1];
    } else {
        e0 = ((const int*)idxp)[b * 2 + 0];
        e1 = ((const int*)idxp)[b * 2 + 1];
    }
    float w0 = rw[b * 2 + 0];
    float w1 = rw[b * 2 + 1];
    if (e0 == e1) {
        int p = atomicAdd(&g_cnt[e0], 1);
        g_tok[e0][p] = b; g_wgt[e0][p] = w0 + w1;
    } else {
        int p = atomicAdd(&g_cnt[e0], 1);
        g_tok[e0][p] = b; g_wgt[e0][p] = w0;
        p = atomicAdd(&g_cnt[e1], 1);
        g_tok[e1][p] = b; g_wgt[e1][p] = w1;
    }
}

// fp32 -> fp16 converter with device-side source select:
// which==1 -> convert the W1 buffer, which==2 -> the W2 buffer (per g_flags[2])
__global__ void k_cvt_w(const float4* __restrict__ A, const float4* __restrict__ B,
                        uint4* __restrict__ dst, int n8, int which) {
    const float4* src = ((g_flags[2] != 0) == (which == 1)) ? A : B;
    int i = blockIdx.x * blockDim.x + threadIdx.x;
    int stride = gridDim.x * blockDim.x;
    for (; i < n8; i += stride) {
        float4 v0 = src[i * 2], v1 = src[i * 2 + 1];
        __half2 h0 = __floats2half2_rn(v0.x, v0.y);
        __half2 h1 = __floats2half2_rn(v0.z, v0.w);
        __half2 h2 = __floats2half2_rn(v1.x, v1.y);
        __half2 h3 = __floats2half2_rn(v1.z, v1.w);
        uint4 o;
        o.x = *(uint32_t*)&h0; o.y = *(uint32_t*)&h1;
        o.z = *(uint32_t*)&h2; o.w = *(uint32_t*)&h3;
        dst[i] = o;
    }
}

__global__ void k_cvt(const float4* __restrict__ src, uint4* __restrict__ dst,
                      int n8) {
    int i = blockIdx.x * blockDim.x + threadIdx.x;
    int stride = gridDim.x * blockDim.x;
    for (; i < n8; i += stride) {
        float4 v0 = src[i * 2], v1 = src[i * 2 + 1];
        __half2 h0 = __floats2half2_rn(v0.x, v0.y);
        __half2 h1 = __floats2half2_rn(v0.z, v0.w);
        __half2 h2 = __floats2half2_rn(v1.x, v1.y);
        __half2 h3 = __floats2half2_rn(v1.z, v1.w);
        uint4 o;
        o.x = *(uint32_t*)&h0; o.y = *(uint32_t*)&h1;
        o.z = *(uint32_t*)&h2; o.w = *(uint32_t*)&h3;
        dst[i] = o;
    }
}

// ---------------------------------------------------------------------------
// GEMM1: H[e,pos,f] = silu(X[tok] . W1[e][:,f]); 256 thr, CTA 64x128, 2 CTA/SM
__global__ __launch_bounds__(256, 2)
void k_gemm1() {
    int e    = blockIdx.z;
    int cnt  = g_cnt[e];
    int row0 = blockIdx.y * 64;
    if (row0 >= cnt) return;
    int col0 = blockIdx.x * 128;

    extern __shared__ char dyn[];
    __shared__ int stok[64];

    int tid = threadIdx.x, lane = tid & 31, wid = tid >> 5;
    if (tid < 64) {
        int r = row0 + tid;
        stok[tid] = (r < cnt) ? g_tok[e][r] : 0;
    }
    __syncthreads();

    const __half* W = g_W1h + (size_t)e * HID * FFN + col0;
    uint32_t sb = smem_u32(dyn);

    int arow = tid >> 2, aoff = (tid & 3) * 8;
    const __half* Asrc = g_Xh + (size_t)stok[arow] * HID + aoff;
    int brow = tid >> 4, bch = (tid & 15) * 8;
    const __half* Bsrc = W + (size_t)brow * FFN + bch;

    uint32_t adst  = (uint32_t)(arow * ASTR + aoff) * 2;
    uint32_t bdst0 = (uint32_t)(ASZ) + (uint32_t)(brow * BSTR + bch) * 2;
    uint32_t bdst1 = (uint32_t)(ASZ) + (uint32_t)((brow + 16) * BSTR + bch) * 2;

    int wm = wid & 1, wn = wid >> 1;
    int grp = lane >> 2, tid4 = lane & 3;
    uint32_t aoffB = (uint32_t)(((wm * 32 + (lane & 15)) * ASTR) + ((lane >> 4) * 8)) * 2;
    uint32_t boffB = (uint32_t)(ASZ) +
                     (uint32_t)((((lane & 7) + ((lane >> 3) & 1) * 8) * BSTR) +
                                wn * 32 + (lane >> 4) * 8) * 2;

    const int NIT = HID / 32;

#pragma unroll
    for (int s = 0; s < 2; s++) {
        uint32_t st = sb + s * STG;
        int k0 = s * 32;
        cp16(st + adst, Asrc + k0);
        cp16(st + bdst0, Bsrc + (size_t)k0 * FFN);
        cp16(st + bdst1, Bsrc + (size_t)(k0 + 16) * FFN);
        cp_commit();
    }

    float acc[2][4][4] = {};
    int stg = 0;
    for (int it = 0; it < NIT; it++) {
        cp_wait1();
        __syncthreads();
        if (it + 2 < NIT) {
            uint32_t st = sb + ((stg + 2) % NSTG) * STG;
            int k0 = (it + 2) * 32;
            cp16(st + adst, Asrc + k0);
            cp16(st + bdst0, Bsrc + (size_t)k0 * FFN);
            cp16(st + bdst1, Bsrc + (size_t)(k0 + 16) * FFN);
        }
        cp_commit();

        uint32_t aB = sb + stg * STG + aoffB;
        uint32_t bB = sb + stg * STG + boffB;
#pragma unroll
        for (int kk = 0; kk < 2; kk++) {
            unsigned afr[2][4];
            ldsm_x4(afr[0], aB + kk * 32);
            ldsm_x4(afr[1], aB + 16 * ASTR * 2 + kk * 32);
            unsigned bfr[4][2];
#pragma unroll
            for (int j2 = 0; j2 < 2; j2++) {
                unsigned t[4];
                ldsm_x4_t(t, bB + kk * 16 * BSTR * 2 + j2 * 32);
                bfr[j2 * 2][0] = t[0]; bfr[j2 * 2][1] = t[1];
                bfr[j2 * 2 + 1][0] = t[2]; bfr[j2 * 2 + 1][1] = t[3];
            }
#pragma unroll
            for (int mt = 0; mt < 2; mt++)
#pragma unroll
                for (int j = 0; j < 4; j++)
                    mma16816(acc[mt][j], afr[mt], bfr[j]);
        }
        stg = (stg + 1) % NSTG;
    }

#pragma unroll
    for (int mt = 0; mt < 2; mt++) {
        int rb = row0 + wm * 32 + mt * 16 + grp;
#pragma unroll
        for (int j = 0; j < 4; j++) {
            int cg = col0 + wn * 32 + j * 8 + tid4 * 2;
            float* c = acc[mt][j];
            if (rb < cnt) {
                __half2* Hr = (__half2*)(g_H + ((size_t)e * BATCH + rb) * FFN + cg);
                *Hr = __floats2half2_rn(silu(c[0]), silu(c[1]));
            }
            if (rb + 8 < cnt) {
                __half2* Hr = (__half2*)(g_H + ((size_t)e * BATCH + rb + 8) * FFN + cg);
                *Hr = __floats2half2_rn(silu(c[2]), silu(c[3]));
            }
        }
    }
}

// ---------------------------------------------------------------------------
// GEMM2: out[tok] += wgt * (H[e,pos,:] . W2[e][:,h]); 256 thr, 64x128, 2 CTA/SM
__global__ __launch_bounds__(256, 2)
void k_gemm2(float* __restrict__ out) {
    int e    = blockIdx.z;
    int cnt  = g_cnt[e];
    int row0 = blockIdx.y * 64;
    if (row0 >= cnt) return;
    int col0 = blockIdx.x * 128;

    extern __shared__ char dyn[];
    __shared__ int   stok[64];
    __shared__ float swt[64];

    int tid = threadIdx.x, lane = tid & 31, wid = tid >> 5;
    if (tid < 64) {
        int r = row0 + tid;
        stok[tid] = (r < cnt) ? g_tok[e][r] : 0;
        swt[tid]  = (r < cnt) ? g_wgt[e][r] : 0.0f;
    }
    __syncthreads();

    const __half* W = g_W2h + (size_t)e * HID * FFN + col0;
    uint32_t sb = smem_u32(dyn);

    int arow = tid >> 2, aoff = (tid & 3) * 8;
    const __half* Asrc = g_H + ((size_t)e * BATCH + row0 + arow) * FFN + aoff;
    int brow = tid >> 4, bch = (tid & 15) * 8;
    const __half* Bsrc = W + (size_t)brow * HID + bch;

    uint32_t adst  = (uint32_t)(arow * ASTR + aoff) * 2;
    uint32_t bdst0 = (uint32_t)(ASZ) + (uint32_t)(brow * BSTR + bch) * 2;
    uint32_t bdst1 = (uint32_t)(ASZ) + (uint32_t)((brow + 16) * BSTR + bch) * 2;

    int wm = wid & 1, wn = wid >> 1;
    int grp = lane >> 2, tid4 = lane & 3;
    uint32_t aoffB = (uint32_t)(((wm * 32 + (lane & 15)) * ASTR) + ((lane >> 4) * 8)) * 2;
    uint32_t boffB = (uint32_t)(ASZ) +
                     (uint32_t)((((lane & 7) + ((lane >> 3) & 1) * 8) * BSTR) +
                                wn * 32 + (lane >> 4) * 8) * 2;

    const int NIT = FFN / 32;

#pragma unroll
    for (int s = 0; s < 2; s++) {
        uint32_t st = sb + s * STG;
        int k0 = s * 32;
        cp16(st + adst, Asrc + k0);
        cp16(st + bdst0, Bsrc + (size_t)k0 * HID);
        cp16(st + bdst1, Bsrc + (size_t)(k0 + 16) * HID);
        cp_commit();
    }

    float acc[2][4][4] = {};
    int stg = 0;
    for (int it = 0; it < NIT; it++) {
        cp_wait1();
        __syncthreads();
        if (it + 2 < NIT) {
            uint32_t st = sb + ((stg + 2) % NSTG) * STG;
            int k0 = (it + 2) * 32;
            cp16(st + adst, Asrc + k0);
            cp16(st + bdst0, Bsrc + (size_t)k0 * HID);
            cp16(st + bdst1, Bsrc + (size_t)(k0 + 16) * HID);
        }
        cp_commit();

        uint32_t aB = sb + stg * STG + aoffB;
        uint32_t bB = sb + stg * STG + boffB;
#pragma unroll
        for (int kk = 0; kk < 2; kk++) {
            unsigned afr[2][4];
            ldsm_x4(afr[0], aB + kk * 32);
            ldsm_x4(afr[1], aB + 16 * ASTR * 2 + kk * 32);
            unsigned bfr[4][2];
#pragma unroll
            for (int j2 = 0; j2 < 2; j2++) {
                unsigned t[4];
                ldsm_x4_t(t, bB + kk * 16 * BSTR * 2 + j2 * 32);
                bfr[j2 * 2][0] = t[0]; bfr[j2 * 2][1] = t[1];
                bfr[j2 * 2 + 1][0] = t[2]; bfr[j2 * 2 + 1][1] = t[3];
            }
#pragma unroll
            for (int mt = 0; mt < 2; mt++)
#pragma unroll
                for (int j = 0; j < 4; j++)
                    mma16816(acc[mt][j], afr[mt], bfr[j]);
        }
        stg = (stg + 1) % NSTG;
    }

#pragma unroll
    for (int mt = 0; mt < 2; mt++) {
        int lr = wm * 32 + mt * 16 + grp;
#pragma unroll
        for (int j = 0; j < 4; j++) {
            int cg = col0 + wn * 32 + j * 8 + tid4 * 2;
            float* c = acc[mt][j];
            if (row0 + lr < cnt) {
                int   t = stok[lr];
                float w = swt[lr];
                atomicAdd(&out[(size_t)t * HID + cg],     w * c[0]);
                atomicAdd(&out[(size_t)t * HID + cg + 1], w * c[1]);
            }
            if (row0 + lr + 8 < cnt) {
                int   t = stok[lr + 8];
                float w = swt[lr + 8];
                atomicAdd(&out[(size_t)t * HID + cg],     w * c[2]);
                atomicAdd(&out[(size_t)t * HID + cg + 1], w * c[3]);
            }
        }
    }
}

// ---------------------------------------------------------------------------
extern "C" void kernel_launch(void* const* d_in, const int* in_sizes, int n_in,
                              void* d_out, int out_size) {
    const float* X = nullptr;
    const void*  smallbuf[2] = {nullptr, nullptr};
    const float* bigbuf[2]   = {nullptr, nullptr};
    int ns = 0, nb = 0;
    for (int i = 0; i < n_in; i++) {
        long long s = in_sizes[i];
        if (s == (long long)BATCH * HID)            X = (const float*)d_in[i];
        else if (s == (long long)BATCH * 2)         { if (ns < 2) smallbuf[ns++] = d_in[i]; }
        else if (s == (long long)NE * HID * FFN)    { if (nb < 2) bigbuf[nb++] = (const float*)d_in[i]; }
    }
    float* out = (float*)d_out;

    cudaFuncSetAttribute(k_gemm1, cudaFuncAttributeMaxDynamicSharedMemorySize, SMEM_BYTES);
    cudaFuncSetAttribute(k_gemm2, cudaFuncAttributeMaxDynamicSharedMemorySize, SMEM_BYTES);

    __half *dW1, *dW2, *dXh;
    cudaGetSymbolAddress((void**)&dW1, g_W1h);
    cudaGetSymbolAddress((void**)&dW2, g_W2h);
    cudaGetSymbolAddress((void**)&dXh, g_Xh);

    // fork/join resources (host objects only; created per call, not destroyed
    // while capture is active — a few leaked handles over the run is fine)
    cudaStream_t s2;
    cudaEvent_t  e1, e2;
    cudaStreamCreateWithFlags(&s2, cudaStreamNonBlocking);
    cudaEventCreateWithFlags(&e1, cudaEventDisableTiming);
    cudaEventCreateWithFlags(&e2, cudaEventDisableTiming);

    int n8w = NE * HID * FFN / 8;

    cudaMemsetAsync(out, 0, (size_t)out_size * sizeof(float));
    k_detect<<<1, 256>>>((const unsigned*)smallbuf[0], (const unsigned*)smallbuf[1],
                         bigbuf[0], bigbuf[1]);
    k_route<<<(BATCH + 255) / 256, 256>>>(smallbuf[0], smallbuf[1]);

    // critical path: W1 + X converts
    k_cvt_w<<<1184, 256>>>((const float4*)bigbuf[0], (const float4*)bigbuf[1],
                           (uint4*)dW1, n8w, 1);
    k_cvt<<<256, 256>>>((const float4*)X, (uint4*)dXh, BATCH * HID / 8);

    // fork: W2 convert overlaps GEMM1
    cudaEventRecord(e1, 0);
    cudaStreamWaitEvent(s2, e1, 0);
    k_cvt_w<<<1184, 256, 0, s2>>>((const float4*)bigbuf[0], (const float4*)bigbuf[1],
                                  (uint4*)dW2, n8w, 2);
    cudaEventRecord(e2, s2);

    k_gemm1<<<dim3(FFN / 128, BATCH / 64, NE), 256, SMEM_BYTES>>>();

    // join before GEMM2
    cudaStreamWaitEvent(0, e2, 0);
    k_gemm2<<<dim3(HID / 128, BATCH / 64, NE), 256, SMEM_BYTES>>>(out);
}